// round 2
// baseline (speedup 1.0000x reference)
#include <cuda_runtime.h>
#include <math.h>

#define BB 4
#define NN 2048
#define KK 30
#define HH 128
#define NNODES (BB*NN)

// ---------------- device scratch ----------------
__device__ float g_hV  [NNODES*HH];
__device__ float g_Apre[NNODES*HH];
__device__ float g_Cpre[NNODES*HH];
__device__ float g_Q   [NNODES*9];
__device__ float g_msg [NNODES*HH];
__device__ float g_hV1 [NNODES*HH];
__device__ float g_tmp [NNODES*HH];
__device__ float g_Wef [16*HH];
__device__ float g_bef [HH];

// ---------------- helpers ----------------
struct F3{float x,y,z;};
__device__ __forceinline__ F3 f3(float a,float b,float c){F3 r;r.x=a;r.y=b;r.z=c;return r;}
__device__ __forceinline__ F3 sub3(F3 a,F3 b){return f3(a.x-b.x,a.y-b.y,a.z-b.z);}
__device__ __forceinline__ float dot3(F3 a,F3 b){return a.x*b.x+a.y*b.y+a.z*b.z;}
__device__ __forceinline__ F3 cross3(F3 a,F3 b){
  return f3(a.y*b.z-a.z*b.y, a.z*b.x-a.x*b.z, a.x*b.y-a.y*b.x);
}
__device__ __forceinline__ F3 norm3(F3 v){
  float n=dot3(v,v);
  if(n>0.f){float r=rsqrtf(n);return f3(v.x*r,v.y*r,v.z*r);}
  return f3(0.f,0.f,0.f);
}
__device__ __forceinline__ float sgnf(float x){return (x>0.f)?1.f:((x<0.f)?-1.f:0.f);}
__device__ __forceinline__ float gelu(float x){return 0.5f*x*(1.f+erff(x*0.7071067811865475f));}
__device__ __forceinline__ float clip1(float x){return fminf(fmaxf(x,-1.f+1e-7f),1.f-1e-7f);}
// Xf[f] = X[b][f/3][f%3][:]   (X is (B,N,4,3))
__device__ __forceinline__ F3 loadXf(const float* X,int b,int f){
  const float* p=X+(((b*NN)+(f/3))*4+(f%3))*3;
  return f3(p[0],p[1],p[2]);
}

// ---------------- kernel 0: fold We through W1's hE block ----------------
__global__ void k_fold(const float* __restrict__ Wew,const float* __restrict__ Web,
                       const float* __restrict__ W1w,const float* __restrict__ W1b){
  int j=threadIdx.x; int kb=blockIdx.x;
  if(kb<16){
    float s=0.f;
    for(int m=0;m<128;m++) s+=Wew[kb*128+m]*W1w[(128+m)*128+j];
    g_Wef[kb*128+j]=s;
  }else{
    float s=W1b[j];
    for(int m=0;m<128;m++) s+=Web[m]*W1w[(128+m)*128+j];
    g_bef[j]=s;
  }
}

// ---------------- kernel 1: node geometry + hV + Apre/Cpre ----------------
__global__ void k_node(const float* __restrict__ X,const float* __restrict__ Wvw,
                       const float* __restrict__ Wvb,const float* __restrict__ W1w){
  __shared__ float sfeat[32][21];
  __shared__ float sQ[32][9];
  __shared__ float shv[32][128];
  int t=threadIdx.x; int base=blockIdx.x*32;

  if(t<96){
    // dihedral + bond-angle features, (node, c) per thread
    int nl=t/3, c=t-nl*3; int g=base+nl; int b=g>>11, n=g&(NN-1);
    int tt=3*n+c-1;
    float cD=1.f,sD=0.f,cA=1.f,sA=0.f;
    if(tt>=0 && tt<=3*NN-4){
      F3 x0=loadXf(X,b,tt),x1=loadXf(X,b,tt+1),x2=loadXf(X,b,tt+2),x3=loadXf(X,b,tt+3);
      F3 u0=norm3(sub3(x1,x0)),u1=norm3(sub3(x2,x1)),u2=norm3(sub3(x3,x2));
      F3 n0=norm3(cross3(u0,u1)),n1=norm3(cross3(u1,u2));
      float cd=clip1(dot3(n0,n1));
      F3 v=norm3(cross3(n0,n1));
      float sg=sgnf(-dot3(v,u1));
      cD=(sg==0.f)?1.f:cd;
      sD=sg*sqrtf(fmaxf(0.f,1.f-cd*cd));
      float ca=clip1(dot3(u0,u1));
      cA=ca; sA=sqrtf(fmaxf(0.f,1.f-ca*ca));
    }
    sfeat[nl][c]=cD; sfeat[nl][3+c]=sD; sfeat[nl][6+c]=cA; sfeat[nl][9+c]=sA;
  }else if(t<128){
    // local frame Q per node
    int nl=t-96; int g=base+nl; int b=g>>11, n=g&(NN-1);
    float Qr[9];
    if(n==NN-1){
      #pragma unroll
      for(int k2=0;k2<9;k2++)Qr[k2]=0.f;
    }else{
      F3 x0=loadXf(X,b,3*n),x1=loadXf(X,b,3*n+1),x2=loadXf(X,b,3*n+2);
      F3 u0=norm3(sub3(x1,x0)),u1=norm3(sub3(x2,x1));
      F3 n0=norm3(cross3(u0,u1)),b1=norm3(sub3(u0,u1));
      F3 r2=cross3(b1,n0);
      Qr[0]=b1.x;Qr[1]=b1.y;Qr[2]=b1.z;
      Qr[3]=n0.x;Qr[4]=n0.y;Qr[5]=n0.z;
      Qr[6]=r2.x;Qr[7]=r2.y;Qr[8]=r2.z;
    }
    #pragma unroll
    for(int k2=0;k2<9;k2++){sQ[nl][k2]=Qr[k2];g_Q[g*9+k2]=Qr[k2];}
  }
  __syncthreads();
  if(t<96){
    // V_direct (inner-frame directions to N, C, O) — needs Q
    int nl=t/3, a=t-nl*3; int g=base+nl; int b=g>>11, n=g&(NN-1);
    int atom=(a==0)?0:(a+1);  // atoms {0,2,3}
    const float* Xp=X+((b*NN+n)*4)*3;
    F3 d=f3(Xp[atom*3]-Xp[0],Xp[atom*3+1]-Xp[1],Xp[atom*3+2]-Xp[2]);
    F3 du=f3(sQ[nl][0]*d.x+sQ[nl][1]*d.y+sQ[nl][2]*d.z,
             sQ[nl][3]*d.x+sQ[nl][4]*d.y+sQ[nl][5]*d.z,
             sQ[nl][6]*d.x+sQ[nl][7]*d.y+sQ[nl][8]*d.z);
    du=norm3(du);
    sfeat[nl][12+a*3+0]=du.x; sfeat[nl][12+a*3+1]=du.y; sfeat[nl][12+a*3+2]=du.z;
  }
  __syncthreads();
  // hV = feat @ Wv + b
  int j=t&127, half=t>>7;
  float wv[21];
  #pragma unroll
  for(int i=0;i<21;i++) wv[i]=Wvw[i*128+j];
  float bv=Wvb[j];
  for(int r=0;r<16;r++){
    int nl=half*16+r;
    float a=bv;
    #pragma unroll
    for(int i=0;i<21;i++) a+=sfeat[nl][i]*wv[i];
    shv[nl][j]=a;
    g_hV[(base+nl)*128+j]=a;
  }
  __syncthreads();
  // Apre = hV@W1a (rows 0..127), Cpre = hV@W1c (rows 256..383)
  float accA[16],accC[16];
  #pragma unroll
  for(int r=0;r<16;r++){accA[r]=0.f;accC[r]=0.f;}
  for(int i=0;i<128;i++){
    float wa=W1w[i*128+j], wc=W1w[(256+i)*128+j];
    #pragma unroll
    for(int r=0;r<16;r++){
      float h=shv[half*16+r][i];
      accA[r]+=wa*h; accC[r]+=wc*h;
    }
  }
  for(int r=0;r<16;r++){
    g_Apre[(base+half*16+r)*128+j]=accA[r];
    g_Cpre[(base+half*16+r)*128+j]=accC[r];
  }
}

// ---------------- kernel 2: edge geometry + 3-layer MLP + sum over K ----------------
#define SM_W2   0
#define SM_W3   16384
#define SM_WEF  32768
#define SM_BEF  34816
#define SM_B2   34944
#define SM_B3   35072
#define SM_H1   35200
#define SM_H2   39424
#define SM_E16  43648
#define SM_APB  44160
#define SM_PART 44288
#define SM_NBR  45312
#define EDGE_SMEM_FLOATS 45344

__global__ void k_edge(const float* __restrict__ X,const int* __restrict__ Eidx,
                       const float* __restrict__ W2w,const float* __restrict__ W2b,
                       const float* __restrict__ W3w,const float* __restrict__ W3b){
  extern __shared__ float sm[];
  float* sW2=sm+SM_W2; float* sW3=sm+SM_W3; float* sWef=sm+SM_WEF;
  float* sbef=sm+SM_BEF; float* sb2=sm+SM_B2; float* sb3=sm+SM_B3;
  float* sh1=sm+SM_H1; float* sh2=sm+SM_H2; float* se16=sm+SM_E16;
  float* sApb=sm+SM_APB; float* spart=sm+SM_PART; int* snbr=(int*)(sm+SM_NBR);
  int t=threadIdx.x;
  for(int i=t;i<16384;i+=256){sW2[i]=W2w[i];sW3[i]=W3w[i];}
  for(int i=t;i<2048;i+=256) sWef[i]=g_Wef[i];
  if(t<128){sbef[t]=g_bef[t];sb2[t]=W2b[t];sb3[t]=W3b[t];}
  __syncthreads();
  int jg=t&31, eg=t>>5;

  for(int g=blockIdx.x; g<NNODES; g+=gridDim.x){
    __syncthreads();
    int b=g>>11, n=g&(NN-1);
    if(t>=128){ int j=t-128; sApb[j]=g_Apre[g*128+j]+sbef[j]; }
    if(t<32){
      int e=t;
      int nbr=(e<KK)?Eidx[g*KK+e]:0;
      snbr[e]=nbr;
      float out[16];
      #pragma unroll
      for(int k2=0;k2<16;k2++)out[k2]=0.f;
      if(e<KK){
        const float* Qo=g_Q+g*9;
        F3 q0=f3(Qo[0],Qo[1],Qo[2]),q1=f3(Qo[3],Qo[4],Qo[5]),q2=f3(Qo[6],Qo[7],Qo[8]);
        const float* Xo=X+(b*NN+n)*12;
        F3 xa=f3(Xo[0],Xo[1],Xo[2]);
        const float* Xn=X+(b*NN+nbr)*12;
        const int ord[4]={1,0,2,3}; // CA, N, C, O
        #pragma unroll
        for(int a=0;a<4;a++){
          int atom=ord[a];
          F3 p=f3(Xn[atom*3],Xn[atom*3+1],Xn[atom*3+2]);
          F3 d=sub3(p,xa);
          F3 du=norm3(f3(dot3(q0,d),dot3(q1,d),dot3(q2,d)));
          out[a*3]=du.x; out[a*3+1]=du.y; out[a*3+2]=du.z;
        }
        const float* Qn=g_Q+(b*NN+nbr)*9;
        // R = Qown^T @ Qnbr
        float R00=q0.x*Qn[0]+q1.x*Qn[3]+q2.x*Qn[6];
        float R01=q0.x*Qn[1]+q1.x*Qn[4]+q2.x*Qn[7];
        float R02=q0.x*Qn[2]+q1.x*Qn[5]+q2.x*Qn[8];
        float R10=q0.y*Qn[0]+q1.y*Qn[3]+q2.y*Qn[6];
        float R11=q0.y*Qn[1]+q1.y*Qn[4]+q2.y*Qn[7];
        float R12=q0.y*Qn[2]+q1.y*Qn[5]+q2.y*Qn[8];
        float R20=q0.z*Qn[0]+q1.z*Qn[3]+q2.z*Qn[6];
        float R21=q0.z*Qn[1]+q1.z*Qn[4]+q2.z*Qn[7];
        float R22=q0.z*Qn[2]+q1.z*Qn[5]+q2.z*Qn[8];
        float m0=0.5f*sqrtf(fabsf(1.f+R00-R11-R22));
        float m1=0.5f*sqrtf(fabsf(1.f-R00+R11-R22));
        float m2=0.5f*sqrtf(fabsf(1.f-R00-R11+R22));
        float qx=sgnf(R21-R12)*m0;
        float qy=sgnf(R02-R20)*m1;
        float qz=sgnf(R10-R01)*m2;
        float qw=0.5f*sqrtf(fmaxf(0.f,1.f+R00+R11+R22));
        float nq=qx*qx+qy*qy+qz*qz+qw*qw;
        if(nq>0.f){float r=rsqrtf(nq);qx*=r;qy*=r;qz*=r;qw*=r;}
        else{qx=0.f;qy=0.f;qz=0.f;qw=0.f;}
        out[12]=qx;out[13]=qy;out[14]=qz;out[15]=qw;
      }
      #pragma unroll
      for(int k2=0;k2<16;k2++) se16[e*16+k2]=out[k2];
    }
    __syncthreads();

    // ---- layer 1: gelu(e16@Wef + Apre[g]+bef + Cpre[nbr]) ----
    float a1[4][4];
    #pragma unroll
    for(int e=0;e<4;e++){
      #pragma unroll
      for(int c=0;c<4;c++)a1[e][c]=0.f;
    }
    #pragma unroll
    for(int i=0;i<16;i++){
      float4 w=*(const float4*)&sWef[i*128+jg*4];
      #pragma unroll
      for(int e=0;e<4;e++){
        float x=se16[(eg*4+e)*16+i];
        a1[e][0]+=x*w.x;a1[e][1]+=x*w.y;a1[e][2]+=x*w.z;a1[e][3]+=x*w.w;
      }
    }
    {
      float4 ap=*(const float4*)&sApb[jg*4];
      #pragma unroll
      for(int e=0;e<4;e++){
        int te=eg*4+e;
        const float* Cp=g_Cpre+(b*NN+snbr[te])*128;
        float4 cv=*(const float4*)&Cp[jg*4];
        sh1[te*132+jg*4+0]=gelu(a1[e][0]+ap.x+cv.x);
        sh1[te*132+jg*4+1]=gelu(a1[e][1]+ap.y+cv.y);
        sh1[te*132+jg*4+2]=gelu(a1[e][2]+ap.z+cv.z);
        sh1[te*132+jg*4+3]=gelu(a1[e][3]+ap.w+cv.w);
      }
    }
    __syncthreads();

    // ---- layer 2 ----
    float a2[4][4];
    #pragma unroll
    for(int e=0;e<4;e++){
      a2[e][0]=sb2[jg*4+0];a2[e][1]=sb2[jg*4+1];a2[e][2]=sb2[jg*4+2];a2[e][3]=sb2[jg*4+3];
    }
    #pragma unroll 4
    for(int i=0;i<128;i++){
      float4 w=*(const float4*)&sW2[i*128+jg*4];
      #pragma unroll
      for(int e=0;e<4;e++){
        float h=sh1[(eg*4+e)*132+i];
        a2[e][0]+=h*w.x;a2[e][1]+=h*w.y;a2[e][2]+=h*w.z;a2[e][3]+=h*w.w;
      }
    }
    #pragma unroll
    for(int e=0;e<4;e++){
      int te=eg*4+e;
      #pragma unroll
      for(int c=0;c<4;c++) sh2[te*132+jg*4+c]=gelu(a2[e][c]);
    }
    __syncthreads();

    // ---- layer 3 (bias added at reduce) ----
    float a3[4][4];
    #pragma unroll
    for(int e=0;e<4;e++){
      #pragma unroll
      for(int c=0;c<4;c++)a3[e][c]=0.f;
    }
    #pragma unroll 4
    for(int i=0;i<128;i++){
      float4 w=*(const float4*)&sW3[i*128+jg*4];
      #pragma unroll
      for(int e=0;e<4;e++){
        float h=sh2[(eg*4+e)*132+i];
        a3[e][0]+=h*w.x;a3[e][1]+=h*w.y;a3[e][2]+=h*w.z;a3[e][3]+=h*w.w;
      }
    }
    float s0=0.f,s1=0.f,s2=0.f,s3=0.f;
    #pragma unroll
    for(int e=0;e<4;e++){
      if(eg*4+e<KK){s0+=a3[e][0];s1+=a3[e][1];s2+=a3[e][2];s3+=a3[e][3];}
    }
    spart[eg*128+jg*4+0]=s0; spart[eg*128+jg*4+1]=s1;
    spart[eg*128+jg*4+2]=s2; spart[eg*128+jg*4+3]=s3;
    __syncthreads();
    if(t<128){
      float acc=KK*sb3[t];
      #pragma unroll
      for(int p=0;p<8;p++) acc+=spart[p*128+t];
      g_msg[g*128+t]=acc;
    }
  }
}

// ---------------- LN kernels ----------------
__global__ void k_ln1(const float* __restrict__ gg,const float* __restrict__ bb){
  __shared__ float red[4];
  int g=blockIdx.x; int j=threadIdx.x;
  float x=g_hV[g*128+j]+g_msg[g*128+j]*(1.f/(float)KK);
  float v=x;
  #pragma unroll
  for(int o=16;o;o>>=1) v+=__shfl_xor_sync(0xffffffffu,v,o);
  if((j&31)==0) red[j>>5]=v;
  __syncthreads();
  float m=(red[0]+red[1]+red[2]+red[3])*(1.f/128.f);
  __syncthreads();
  float d=x-m; v=d*d;
  #pragma unroll
  for(int o=16;o;o>>=1) v+=__shfl_xor_sync(0xffffffffu,v,o);
  if((j&31)==0) red[j>>5]=v;
  __syncthreads();
  float var=(red[0]+red[1]+red[2]+red[3])*(1.f/128.f);
  g_hV1[g*128+j]=d*rsqrtf(var+1e-5f)*gg[j]+bb[j];
}

__global__ void k_ln2(const float* __restrict__ gg,const float* __restrict__ bb,
                      float* __restrict__ out){
  __shared__ float red[4];
  int g=blockIdx.x; int j=threadIdx.x;
  float x=g_tmp[g*128+j];
  float v=x;
  #pragma unroll
  for(int o=16;o;o>>=1) v+=__shfl_xor_sync(0xffffffffu,v,o);
  if((j&31)==0) red[j>>5]=v;
  __syncthreads();
  float m=(red[0]+red[1]+red[2]+red[3])*(1.f/128.f);
  __syncthreads();
  float d=x-m; v=d*d;
  #pragma unroll
  for(int o=16;o;o>>=1) v+=__shfl_xor_sync(0xffffffffu,v,o);
  if((j&31)==0) red[j>>5]=v;
  __syncthreads();
  float var=(red[0]+red[1]+red[2]+red[3])*(1.f/128.f);
  out[g*128+j]=d*rsqrtf(var+1e-5f)*gg[j]+bb[j];
}

// ---------------- kernel: FF with smem-staged weight tiles ----------------
#define FF_SMEM_FLOATS 36864
__global__ void k_ff(const float* __restrict__ Wi,const float* __restrict__ bi,
                     const float* __restrict__ Wo,const float* __restrict__ bo){
  extern __shared__ float sm[];
  float* shv1=sm;            // 32*128
  float* shid=sm+4096;       // 32*512
  float* swt =sm+20480;      // 128*128
  int t=threadIdx.x; int base=blockIdx.x*32;
  int j=t&127, half=t>>7;
  for(int idx=t; idx<4096; idx+=256) shv1[idx]=g_hV1[base*128+idx];
  __syncthreads();
  for(int c=0;c<4;c++){
    for(int idx=t; idx<16384; idx+=256){
      int i=idx>>7, m=idx&127;
      swt[idx]=Wi[i*512 + c*128 + m];
    }
    __syncthreads();
    float bj=bi[c*128+j];
    for(int r=0;r<16;r++){
      int nl=half*16+r;
      float acc=bj;
      #pragma unroll 4
      for(int i=0;i<128;i++) acc+=shv1[nl*128+i]*swt[i*128+j];
      shid[nl*512 + c*128 + j]=gelu(acc);
    }
    __syncthreads();
  }
  float o[16];
  float bj=bo[j];
  #pragma unroll
  for(int r=0;r<16;r++)o[r]=bj;
  for(int c=0;c<4;c++){
    for(int idx=t; idx<16384; idx+=256){
      int m=idx>>7, jj=idx&127;
      swt[idx]=Wo[(c*128+m)*128+jj];
    }
    __syncthreads();
    for(int r=0;r<16;r++){
      int nl=half*16+r;
      float acc=0.f;
      #pragma unroll 4
      for(int m=0;m<128;m++) acc+=shid[nl*512+c*128+m]*swt[m*128+j];
      o[r]+=acc;
    }
    __syncthreads();
  }
  for(int r=0;r<16;r++){
    int nl=half*16+r;
    g_tmp[(base+nl)*128+j]=shv1[nl*128+j]+o[r];
  }
}

// ---------------- launch ----------------
extern "C" void kernel_launch(void* const* d_in, const int* in_sizes, int n_in,
                              void* d_out, int out_size){
  const float* X  =(const float*)d_in[0];
  const int*  Eidx=(const int*  )d_in[1];
  const float* Wvw=(const float*)d_in[2];
  const float* Wvb=(const float*)d_in[3];
  const float* Wew=(const float*)d_in[4];
  const float* Web=(const float*)d_in[5];
  const float* W1w=(const float*)d_in[6];
  const float* W1b=(const float*)d_in[7];
  const float* W2w=(const float*)d_in[8];
  const float* W2b=(const float*)d_in[9];
  const float* W3w=(const float*)d_in[10];
  const float* W3b=(const float*)d_in[11];
  const float* Wiw=(const float*)d_in[12];
  const float* Wib=(const float*)d_in[13];
  const float* Wow=(const float*)d_in[14];
  const float* Wob=(const float*)d_in[15];
  const float* l1g=(const float*)d_in[16];
  const float* l1b=(const float*)d_in[17];
  const float* l2g=(const float*)d_in[18];
  const float* l2b=(const float*)d_in[19];
  float* out=(float*)d_out;

  cudaFuncSetAttribute(k_edge, cudaFuncAttributeMaxDynamicSharedMemorySize,
                       EDGE_SMEM_FLOATS*(int)sizeof(float));
  cudaFuncSetAttribute(k_ff, cudaFuncAttributeMaxDynamicSharedMemorySize,
                       FF_SMEM_FLOATS*(int)sizeof(float));

  k_fold<<<17,128>>>(Wew,Web,W1w,W1b);
  k_node<<<NNODES/32,256>>>(X,Wvw,Wvb,W1w);
  k_edge<<<152,256,EDGE_SMEM_FLOATS*sizeof(float)>>>(X,Eidx,W2w,W2b,W3w,W3b);
  k_ln1<<<NNODES,128>>>(l1g,l1b);
  k_ff<<<NNODES/32,256,FF_SMEM_FLOATS*sizeof(float)>>>(Wiw,Wib,Wow,Wob);
  k_ln2<<<NNODES,128>>>(l2g,l2b,out);
}